// round 7
// baseline (speedup 1.0000x reference)
#include <cuda_runtime.h>
#include <math.h>

// Fixed problem shape (ReRanker reference): B=256, C=128, D=1024, fp32.
#define BB 256
#define CC 128
#define DD 1024
#define NQ 4                 // quarters per batch
#define RQ 32                // rows per quarter-task
#define NTASK (BB * NQ)      // 1024 tasks
#define GRID 148             // persistent CTAs, all co-resident (1/SM)
#define NTHR 512
#define NW 16
#define EPS 1e-8f
#define EPS2 1e-16f

// Scratch (device globals — no runtime allocation).
__device__ float g_Spart[BB][NQ][DD];   // 4 MB quarter-partial S
__device__ float g_scpart[BB][NQ];      // partial of sum_c (summ·cand_c)/cn_c
__device__ int   g_flag[BB];            // quarters-done counter per batch

__global__ void k_init_flags() {
    int i = blockIdx.x * blockDim.x + threadIdx.x;
    if (i < BB) g_flag[i] = 0;
}

struct SM {
    float  rows[RQ][DD];     // 128 KB — quarter tile, SMEM-resident
    float4 docs[DD / 4];     // 4 KB
    float4 sums[DD / 4];     // 4 KB
    float  S[DD];            // 4 KB — full-batch S
    float  rcn[RQ];
    float  red[3][8];
    float  wsum[NW];
    float  sc_rdn, sc_rsn;
};

__global__ void __launch_bounds__(NTHR, 1) k_persist(
    const float* __restrict__ doc,
    const float* __restrict__ summ,
    const float* __restrict__ cand,
    float* __restrict__ out)
{
    extern __shared__ char smem_raw[];
    SM* s = reinterpret_cast<SM*>(smem_raw);

    const int tid = threadIdx.x;
    const int w   = tid >> 5;
    const int l   = tid & 31;

    for (int t = blockIdx.x; t < NTASK; t += GRID) {
        const int b = t >> 2;
        const int q = t & 3;

        // ---------- phase 0: doc/summary norms (first 8 warps) ----------
        if (tid < 256) {
            const float4* docg = (const float4*)(doc  + (size_t)b * DD);
            const float4* sumg = (const float4*)(summ + (size_t)b * DD);
            float4 dv = __ldg(docg + tid);
            float4 sv = __ldg(sumg + tid);
            s->docs[tid] = dv;
            s->sums[tid] = sv;
            float pdd = dv.x*dv.x + dv.y*dv.y + dv.z*dv.z + dv.w*dv.w;
            float pss = sv.x*sv.x + sv.y*sv.y + sv.z*sv.z + sv.w*sv.w;
            float pds = dv.x*sv.x + dv.y*sv.y + dv.z*sv.z + dv.w*sv.w;
            #pragma unroll
            for (int o = 16; o; o >>= 1) {
                pdd += __shfl_xor_sync(0xffffffffu, pdd, o);
                pss += __shfl_xor_sync(0xffffffffu, pss, o);
                pds += __shfl_xor_sync(0xffffffffu, pds, o);
            }
            if (l == 0) { s->red[0][w] = pdd; s->red[1][w] = pss; s->red[2][w] = pds; }
        }
        __syncthreads();
        if (tid == 0) {
            float dd = 0.f, ss = 0.f, ds = 0.f;
            #pragma unroll
            for (int i = 0; i < 8; i++) { dd += s->red[0][i]; ss += s->red[1][i]; ds += s->red[2][i]; }
            float dn = fmaxf(sqrtf(dd), EPS);
            float sn = fmaxf(sqrtf(ss), EPS);
            s->sc_rdn = 1.0f / dn;
            s->sc_rsn = 1.0f / sn;
            if (q == 0)
                out[2 * BB * CC + b] = ds / (dn * sn);        // summary_score[b]
        }
        __syncthreads();
        const float rdn = s->sc_rdn;

        // ---------- phase 1: load 2 rows/warp, store SMEM, norms/outer ----------
        const float* cb = cand + (size_t)(b * CC + q * RQ) * DD;
        {
            const int r0 = 2 * w, r1 = 2 * w + 1;
            const float4* p0 = (const float4*)(cb + (size_t)r0 * DD);
            const float4* p1 = (const float4*)(cb + (size_t)r1 * DD);
            float4 v0[8], v1[8];
            #pragma unroll
            for (int i = 0; i < 8; i++) { v0[i] = __ldg(p0 + i * 32 + l); v1[i] = __ldg(p1 + i * 32 + l); }
            float4* rs0 = (float4*)s->rows[r0];
            float4* rs1 = (float4*)s->rows[r1];
            #pragma unroll
            for (int i = 0; i < 8; i++) { rs0[i * 32 + l] = v0[i]; rs1[i * 32 + l] = v1[i]; }

            float scpart = 0.f;
            #pragma unroll
            for (int rr = 0; rr < 2; rr++) {
                float4* v = rr ? v1 : v0;
                float ss0 = 0.f, ss1 = 0.f, dd0 = 0.f, dd1 = 0.f, sd0 = 0.f, sd1 = 0.f;
                #pragma unroll
                for (int i = 0; i < 8; i += 2) {
                    float4 a  = v[i];
                    float4 d4 = s->docs[i * 32 + l];
                    float4 s4 = s->sums[i * 32 + l];
                    ss0 = fmaf(a.x, a.x, ss0); ss0 = fmaf(a.y, a.y, ss0);
                    ss0 = fmaf(a.z, a.z, ss0); ss0 = fmaf(a.w, a.w, ss0);
                    dd0 = fmaf(a.x, d4.x, dd0); dd0 = fmaf(a.y, d4.y, dd0);
                    dd0 = fmaf(a.z, d4.z, dd0); dd0 = fmaf(a.w, d4.w, dd0);
                    sd0 = fmaf(a.x, s4.x, sd0); sd0 = fmaf(a.y, s4.y, sd0);
                    sd0 = fmaf(a.z, s4.z, sd0); sd0 = fmaf(a.w, s4.w, sd0);
                    float4 a1  = v[i + 1];
                    float4 d41 = s->docs[(i + 1) * 32 + l];
                    float4 s41 = s->sums[(i + 1) * 32 + l];
                    ss1 = fmaf(a1.x, a1.x, ss1); ss1 = fmaf(a1.y, a1.y, ss1);
                    ss1 = fmaf(a1.z, a1.z, ss1); ss1 = fmaf(a1.w, a1.w, ss1);
                    dd1 = fmaf(a1.x, d41.x, dd1); dd1 = fmaf(a1.y, d41.y, dd1);
                    dd1 = fmaf(a1.z, d41.z, dd1); dd1 = fmaf(a1.w, d41.w, dd1);
                    sd1 = fmaf(a1.x, s41.x, sd1); sd1 = fmaf(a1.y, s41.y, sd1);
                    sd1 = fmaf(a1.z, s41.z, sd1); sd1 = fmaf(a1.w, s41.w, sd1);
                }
                float ss = ss0 + ss1, ddv = dd0 + dd1, sd = sd0 + sd1;
                #pragma unroll
                for (int o = 16; o; o >>= 1) {
                    ss  += __shfl_xor_sync(0xffffffffu, ss, o);
                    ddv += __shfl_xor_sync(0xffffffffu, ddv, o);
                    sd  += __shfl_xor_sync(0xffffffffu, sd, o);
                }
                float rcn = rsqrtf(fmaxf(ss, EPS2));
                const int rl = rr ? r1 : r0;
                if (l == 0) {
                    out[b * CC + q * RQ + rl] = ddv * rcn * rdn;   // outer_score
                    s->rcn[rl] = rcn;
                }
                scpart = fmaf(sd, rcn, scpart);
            }
            if (l == 0) s->wsum[w] = scpart;
        }
        __syncthreads();

        // ---------- build quarter-partial S from SMEM rows; publish ----------
        {
            const int d0 = 2 * tid;
            float a0 = 0.f, a1 = 0.f;
            #pragma unroll
            for (int r = 0; r < RQ; r++) {
                float rc = s->rcn[r];
                a0 = fmaf(s->rows[r][d0],     rc, a0);
                a1 = fmaf(s->rows[r][d0 + 1], rc, a1);
            }
            *(float2*)&g_Spart[b][q][d0] = make_float2(a0, a1);
        }
        if (tid == 0) {
            float acc = 0.f;
            #pragma unroll
            for (int i = 0; i < NW; i++) acc += s->wsum[i];
            g_scpart[b][q] = acc;
        }
        __syncthreads();
        if (tid == 0) {
            __threadfence();                 // release: Spart/scpart visible
            atomicAdd(&g_flag[b], 1);
        }

        // ---------- prefetch next task's rows into L2 (keeps DRAM busy) ----------
        {
            int tn = t + GRID;
            if (tn < NTASK) {
                const char* np = (const char*)(cand +
                    (size_t)((tn >> 2) * CC + (tn & 3) * RQ) * DD) + (size_t)tid * 256;
                asm volatile("prefetch.global.L2 [%0];"     :: "l"(np));
                asm volatile("prefetch.global.L2 [%0+128];" :: "l"(np));
            }
        }

        // ---------- wait for all 4 quarters of this batch ----------
        if (tid == 0) {
            while (atomicAdd(&g_flag[b], 0) < NQ) { }
            __threadfence();                 // acquire
        }
        __syncthreads();

        // ---------- phase 2: S = sum of quarter partials; inner scores ----------
        {
            const int d0 = 2 * tid;
            float a0 = 0.f, a1 = 0.f;
            #pragma unroll
            for (int qq = 0; qq < NQ; qq++) {
                float2 v = *(const float2*)&g_Spart[b][qq][d0];
                a0 += v.x; a1 += v.y;
            }
            s->S[d0] = a0; s->S[d0 + 1] = a1;
        }
        __syncthreads();

        #pragma unroll
        for (int rr = 0; rr < 2; rr++) {
            const int r = 2 * w + rr;
            const float* row = s->rows[r];
            float dot0 = 0.f, dot1 = 0.f;
            #pragma unroll
            for (int k = 0; k < 32; k += 2) {
                dot0 = fmaf(row[l + 32 * k],       s->S[l + 32 * k],       dot0);
                dot1 = fmaf(row[l + 32 * (k + 1)], s->S[l + 32 * (k + 1)], dot1);
            }
            float dot = dot0 + dot1;
            #pragma unroll
            for (int o = 16; o; o >>= 1)
                dot += __shfl_xor_sync(0xffffffffu, dot, o);
            if (l == 0) {
                // chat_r · S includes the self term (==1 up to fp32 rounding)
                out[BB * CC + b * CC + q * RQ + r] =
                    (dot * s->rcn[r] - 1.0f) * (1.0f / (CC - 1));
            }
        }

        if (q == 0 && tid == 0) {
            float acc = g_scpart[b][0] + g_scpart[b][1] + g_scpart[b][2] + g_scpart[b][3];
            out[2 * BB * CC + BB + b] = acc * s->sc_rsn * (1.0f / CC);   // summary_avg
        }
        __syncthreads();   // rows/S reads done before next task overwrites SMEM
    }
}

extern "C" void kernel_launch(void* const* d_in, const int* in_sizes, int n_in,
                              void* d_out, int out_size) {
    const float* doc  = (const float*)d_in[0];   // [B, D]
    const float* summ = (const float*)d_in[1];   // [B, D]
    const float* cand = (const float*)d_in[2];   // [B, C, D]
    float* out = (float*)d_out;                  // [B*C | B*C | B | B]
    (void)in_sizes; (void)n_in; (void)out_size;

    cudaFuncSetAttribute(k_persist,
                         cudaFuncAttributeMaxDynamicSharedMemorySize,
                         (int)sizeof(SM));

    k_init_flags<<<1, BB>>>();
    k_persist<<<GRID, NTHR, sizeof(SM)>>>(doc, summ, cand, out);
}

// round 8
// speedup vs baseline: 1.0407x; 1.0407x over previous
#include <cuda_runtime.h>
#include <math.h>

// Fixed problem shape (ReRanker reference): B=256, C=128, D=1024, fp32.
#define BB 256
#define CC 128
#define DD 1024
#define NCH 8                // chunks per batch
#define RCH 16               // rows per chunk
#define NTASK (BB * NCH)     // 2048 tasks
#define GRID 296             // persistent CTAs, 2/SM, all co-resident
#define NTHR 256
#define NW 8
#define EPS 1e-8f
#define EPS2 1e-16f

// Scratch (device globals — no runtime allocation).
__device__ float g_Spart[BB][NCH][DD];  // 8 MB chunk-partial S
__device__ float g_scpart[BB][NCH];     // partial of sum_c (summ·cand_c)/cn_c
__device__ int   g_flag[BB];            // chunks-done counter per batch

__global__ void k_init_flags() {
    int i = blockIdx.x * blockDim.x + threadIdx.x;
    if (i < BB) g_flag[i] = 0;
}

struct SM {
    float  rows[RCH][DD];    // 64 KB — chunk tile, SMEM-resident
    float4 docs[DD / 4];     // 4 KB
    float4 sums[DD / 4];     // 4 KB
    float  S[DD];            // 4 KB — full-batch S
    float  rcn[RCH];
    float  red[3][NW];
    float  wsum[NW];
    float  sc_rdn, sc_rsn;
};

__global__ void __launch_bounds__(NTHR, 2) k_persist(
    const float* __restrict__ doc,
    const float* __restrict__ summ,
    const float* __restrict__ cand,
    float* __restrict__ out)
{
    extern __shared__ char smem_raw[];
    SM* s = reinterpret_cast<SM*>(smem_raw);

    const int tid = threadIdx.x;
    const int w   = tid >> 5;
    const int l   = tid & 31;

    for (int t = blockIdx.x; t < NTASK; t += GRID) {
        const int b  = t >> 3;
        const int ch = t & 7;

        // ---------- phase 0: doc/summary norms ----------
        {
            const float4* docg = (const float4*)(doc  + (size_t)b * DD);
            const float4* sumg = (const float4*)(summ + (size_t)b * DD);
            float4 dv = __ldg(docg + tid);
            float4 sv = __ldg(sumg + tid);
            s->docs[tid] = dv;
            s->sums[tid] = sv;
            float pdd = dv.x*dv.x + dv.y*dv.y + dv.z*dv.z + dv.w*dv.w;
            float pss = sv.x*sv.x + sv.y*sv.y + sv.z*sv.z + sv.w*sv.w;
            float pds = dv.x*sv.x + dv.y*sv.y + dv.z*sv.z + dv.w*sv.w;
            #pragma unroll
            for (int o = 16; o; o >>= 1) {
                pdd += __shfl_xor_sync(0xffffffffu, pdd, o);
                pss += __shfl_xor_sync(0xffffffffu, pss, o);
                pds += __shfl_xor_sync(0xffffffffu, pds, o);
            }
            if (l == 0) { s->red[0][w] = pdd; s->red[1][w] = pss; s->red[2][w] = pds; }
        }
        __syncthreads();
        if (tid == 0) {
            float dd = 0.f, ss = 0.f, ds = 0.f;
            #pragma unroll
            for (int i = 0; i < NW; i++) { dd += s->red[0][i]; ss += s->red[1][i]; ds += s->red[2][i]; }
            float dn = fmaxf(sqrtf(dd), EPS);
            float sn = fmaxf(sqrtf(ss), EPS);
            s->sc_rdn = 1.0f / dn;
            s->sc_rsn = 1.0f / sn;
            if (ch == 0)
                out[2 * BB * CC + b] = ds / (dn * sn);        // summary_score[b]
        }
        __syncthreads();
        const float rdn = s->sc_rdn;

        // ---------- phase 1: load 2 rows/warp, store SMEM, norms/outer ----------
        const float* cb = cand + (size_t)(b * CC + ch * RCH) * DD;
        {
            const int r0 = 2 * w, r1 = 2 * w + 1;
            const float4* p0 = (const float4*)(cb + (size_t)r0 * DD);
            const float4* p1 = (const float4*)(cb + (size_t)r1 * DD);
            float4 v0[8], v1[8];
            #pragma unroll
            for (int i = 0; i < 8; i++) { v0[i] = __ldg(p0 + i * 32 + l); v1[i] = __ldg(p1 + i * 32 + l); }
            float4* rs0 = (float4*)s->rows[r0];
            float4* rs1 = (float4*)s->rows[r1];
            #pragma unroll
            for (int i = 0; i < 8; i++) { rs0[i * 32 + l] = v0[i]; rs1[i * 32 + l] = v1[i]; }

            float scpart = 0.f;
            #pragma unroll
            for (int rr = 0; rr < 2; rr++) {
                float4* v = rr ? v1 : v0;
                float ss0 = 0.f, ss1 = 0.f, dd0 = 0.f, dd1 = 0.f, sd0 = 0.f, sd1 = 0.f;
                #pragma unroll
                for (int i = 0; i < 8; i += 2) {
                    float4 a  = v[i];
                    float4 d4 = s->docs[i * 32 + l];
                    float4 s4 = s->sums[i * 32 + l];
                    ss0 = fmaf(a.x, a.x, ss0); ss0 = fmaf(a.y, a.y, ss0);
                    ss0 = fmaf(a.z, a.z, ss0); ss0 = fmaf(a.w, a.w, ss0);
                    dd0 = fmaf(a.x, d4.x, dd0); dd0 = fmaf(a.y, d4.y, dd0);
                    dd0 = fmaf(a.z, d4.z, dd0); dd0 = fmaf(a.w, d4.w, dd0);
                    sd0 = fmaf(a.x, s4.x, sd0); sd0 = fmaf(a.y, s4.y, sd0);
                    sd0 = fmaf(a.z, s4.z, sd0); sd0 = fmaf(a.w, s4.w, sd0);
                    float4 a1  = v[i + 1];
                    float4 d41 = s->docs[(i + 1) * 32 + l];
                    float4 s41 = s->sums[(i + 1) * 32 + l];
                    ss1 = fmaf(a1.x, a1.x, ss1); ss1 = fmaf(a1.y, a1.y, ss1);
                    ss1 = fmaf(a1.z, a1.z, ss1); ss1 = fmaf(a1.w, a1.w, ss1);
                    dd1 = fmaf(a1.x, d41.x, dd1); dd1 = fmaf(a1.y, d41.y, dd1);
                    dd1 = fmaf(a1.z, d41.z, dd1); dd1 = fmaf(a1.w, d41.w, dd1);
                    sd1 = fmaf(a1.x, s41.x, sd1); sd1 = fmaf(a1.y, s41.y, sd1);
                    sd1 = fmaf(a1.z, s41.z, sd1); sd1 = fmaf(a1.w, s41.w, sd1);
                }
                float ss = ss0 + ss1, ddv = dd0 + dd1, sd = sd0 + sd1;
                #pragma unroll
                for (int o = 16; o; o >>= 1) {
                    ss  += __shfl_xor_sync(0xffffffffu, ss, o);
                    ddv += __shfl_xor_sync(0xffffffffu, ddv, o);
                    sd  += __shfl_xor_sync(0xffffffffu, sd, o);
                }
                float rcn = rsqrtf(fmaxf(ss, EPS2));
                const int rl = rr ? r1 : r0;
                if (l == 0) {
                    out[b * CC + ch * RCH + rl] = ddv * rcn * rdn;   // outer_score
                    s->rcn[rl] = rcn;
                }
                scpart = fmaf(sd, rcn, scpart);
            }
            if (l == 0) s->wsum[w] = scpart;
        }
        __syncthreads();

        // ---------- build chunk-partial S from SMEM rows; publish ----------
        {
            const int d0 = 4 * tid;
            float a0 = 0.f, a1 = 0.f, a2 = 0.f, a3 = 0.f;
            #pragma unroll
            for (int r = 0; r < RCH; r++) {
                float rc = s->rcn[r];
                float4 v = *(const float4*)&s->rows[r][d0];
                a0 = fmaf(v.x, rc, a0); a1 = fmaf(v.y, rc, a1);
                a2 = fmaf(v.z, rc, a2); a3 = fmaf(v.w, rc, a3);
            }
            *(float4*)&g_Spart[b][ch][d0] = make_float4(a0, a1, a2, a3);
        }
        if (tid == 0) {
            float acc = 0.f;
            #pragma unroll
            for (int i = 0; i < NW; i++) acc += s->wsum[i];
            g_scpart[b][ch] = acc;
        }
        __syncthreads();
        if (tid == 0) {
            __threadfence();                 // release: Spart/scpart visible
            atomicAdd(&g_flag[b], 1);
            while (atomicAdd(&g_flag[b], 0) < NCH) { }   // wait for all 8 chunks
            __threadfence();                 // acquire
        }
        __syncthreads();

        // ---------- phase 2: S = sum of chunk partials; inner scores ----------
        {
            const int d0 = 4 * tid;
            float a0 = 0.f, a1 = 0.f, a2 = 0.f, a3 = 0.f;
            #pragma unroll
            for (int qq = 0; qq < NCH; qq++) {
                float4 v = *(const float4*)&g_Spart[b][qq][d0];
                a0 += v.x; a1 += v.y; a2 += v.z; a3 += v.w;
            }
            *(float4*)&s->S[d0] = make_float4(a0, a1, a2, a3);
        }
        __syncthreads();

        #pragma unroll
        for (int rr = 0; rr < 2; rr++) {
            const int r = 2 * w + rr;
            const float* row = s->rows[r];
            float dot0 = 0.f, dot1 = 0.f;
            #pragma unroll
            for (int k = 0; k < 32; k += 2) {
                dot0 = fmaf(row[l + 32 * k],       s->S[l + 32 * k],       dot0);
                dot1 = fmaf(row[l + 32 * (k + 1)], s->S[l + 32 * (k + 1)], dot1);
            }
            float dot = dot0 + dot1;
            #pragma unroll
            for (int o = 16; o; o >>= 1)
                dot += __shfl_xor_sync(0xffffffffu, dot, o);
            if (l == 0) {
                // chat_r · S includes the self term (==1 up to fp32 rounding)
                out[BB * CC + b * CC + ch * RCH + r] =
                    (dot * s->rcn[r] - 1.0f) * (1.0f / (CC - 1));
            }
        }

        if (ch == 0 && tid == 0) {
            float acc = 0.f;
            #pragma unroll
            for (int i = 0; i < NCH; i++) acc += g_scpart[b][i];
            out[2 * BB * CC + BB + b] = acc * s->sc_rsn * (1.0f / CC);   // summary_avg
        }
        __syncthreads();   // rows/S reads done before next task overwrites SMEM
    }
}

extern "C" void kernel_launch(void* const* d_in, const int* in_sizes, int n_in,
                              void* d_out, int out_size) {
    const float* doc  = (const float*)d_in[0];   // [B, D]
    const float* summ = (const float*)d_in[1];   // [B, D]
    const float* cand = (const float*)d_in[2];   // [B, C, D]
    float* out = (float*)d_out;                  // [B*C | B*C | B | B]
    (void)in_sizes; (void)n_in; (void)out_size;

    cudaFuncSetAttribute(k_persist,
                         cudaFuncAttributeMaxDynamicSharedMemorySize,
                         (int)sizeof(SM));

    k_init_flags<<<1, BB>>>();
    k_persist<<<GRID, NTHR, sizeof(SM)>>>(doc, summ, cand, out);
}

// round 9
// speedup vs baseline: 1.3067x; 1.2556x over previous
#include <cuda_runtime.h>
#include <math.h>

// Fixed problem shape (ReRanker reference): B=256, C=128, D=1024, fp32.
#define BB 256
#define CC 128
#define DD 1024
#define HR 64                // rows per task (half batch)
#define NW 8                 // 256 threads, 8 warps
#define RPW 8                // rows per warp
#define GRID 296             // persistent CTAs, 2/SM, all co-resident
#define NTASK (BB * 2)       // 512 tasks
#define EPS 1e-8f
#define EPS2 1e-16f

// Scratch (device globals — no runtime allocation).
__device__ float g_Spart[BB][2][DD];    // 2 MB half-batch partial S
__device__ float g_scpart[BB][2];       // partial of sum_c (summ·cand_c)/cn_c
__device__ int   g_flag[BB];            // halves-done counter per batch

__global__ void k_init_flags() {
    int i = blockIdx.x * blockDim.x + threadIdx.x;
    if (i < BB) g_flag[i] = 0;
}

struct F8 { float4 lo, hi; };

__device__ __forceinline__ F8 unpack(unsigned long long u0, unsigned long long u1,
                                     unsigned long long u2, unsigned long long u3) {
    F8 v;
    v.lo.x = __uint_as_float((unsigned)u0); v.lo.y = __uint_as_float((unsigned)(u0 >> 32));
    v.lo.z = __uint_as_float((unsigned)u1); v.lo.w = __uint_as_float((unsigned)(u1 >> 32));
    v.hi.x = __uint_as_float((unsigned)u2); v.hi.y = __uint_as_float((unsigned)(u2 >> 32));
    v.hi.z = __uint_as_float((unsigned)u3); v.hi.w = __uint_as_float((unsigned)(u3 >> 32));
    return v;
}
__device__ __forceinline__ F8 ldg_evict_last(const float* p) {
    unsigned long long u0, u1, u2, u3;
    asm volatile("ld.global.nc.L2::evict_last.v4.b64 {%0,%1,%2,%3}, [%4];"
                 : "=l"(u0), "=l"(u1), "=l"(u2), "=l"(u3) : "l"(p));
    return unpack(u0, u1, u2, u3);
}
__device__ __forceinline__ F8 ldg_evict_first(const float* p) {
    unsigned long long u0, u1, u2, u3;
    asm volatile("ld.global.nc.L2::evict_first.v4.b64 {%0,%1,%2,%3}, [%4];"
                 : "=l"(u0), "=l"(u1), "=l"(u2), "=l"(u3) : "l"(p));
    return unpack(u0, u1, u2, u3);
}

__global__ void __launch_bounds__(256, 2) k_fused(
    const float* __restrict__ doc,
    const float* __restrict__ summ,
    const float* __restrict__ cand,
    float* __restrict__ out)
{
    __shared__ float4 docs[DD / 4];          // 4 KB
    __shared__ float4 sums[DD / 4];          // 4 KB
    __shared__ float4 swp[NW][DD / 4];       // 32 KB warp-private partial S
    __shared__ float4 Ssm[DD / 4];           // 4 KB full S for pass B
    __shared__ float  rcn_s[HR];
    __shared__ float  red[3][NW];
    __shared__ float  wsum[NW];
    __shared__ float  sc_rdn, sc_rsn;

    const int tid = threadIdx.x;
    const int w   = tid >> 5;
    const int l   = tid & 31;

    for (int t = blockIdx.x; t < NTASK; t += GRID) {
        const int b    = t >> 1;
        const int half = t & 1;
        const int row0 = half * HR;

        // ---------- phase 0: doc/summary norms + doc·summary ----------
        {
            const float4* docg = (const float4*)(doc  + (size_t)b * DD);
            const float4* sumg = (const float4*)(summ + (size_t)b * DD);
            float4 dv = __ldg(docg + tid);
            float4 sv = __ldg(sumg + tid);
            docs[tid] = dv;
            sums[tid] = sv;
            float pdd = dv.x*dv.x + dv.y*dv.y + dv.z*dv.z + dv.w*dv.w;
            float pss = sv.x*sv.x + sv.y*sv.y + sv.z*sv.z + sv.w*sv.w;
            float pds = dv.x*sv.x + dv.y*sv.y + dv.z*sv.z + dv.w*sv.w;
            #pragma unroll
            for (int o = 16; o; o >>= 1) {
                pdd += __shfl_xor_sync(0xffffffffu, pdd, o);
                pss += __shfl_xor_sync(0xffffffffu, pss, o);
                pds += __shfl_xor_sync(0xffffffffu, pds, o);
            }
            if (l == 0) { red[0][w] = pdd; red[1][w] = pss; red[2][w] = pds; }
        }
        __syncthreads();
        if (tid == 0) {
            float dd = 0.f, ss = 0.f, ds = 0.f;
            #pragma unroll
            for (int i = 0; i < NW; i++) { dd += red[0][i]; ss += red[1][i]; ds += red[2][i]; }
            float dn = fmaxf(sqrtf(dd), EPS);
            float sn = fmaxf(sqrtf(ss), EPS);
            sc_rdn = 1.0f / dn;
            sc_rsn = 1.0f / sn;
            if (half == 0)
                out[2 * BB * CC + b] = ds / (dn * sn);      // summary_score[b]
        }
        __syncthreads();
        const float rdn = sc_rdn;

        // ---------- pass A: stream 64 rows (evict_last pins in L2) ----------
        const float* cb = cand + ((size_t)b * CC + row0) * DD;
        F8 Sacc[4];
        #pragma unroll
        for (int i = 0; i < 4; i++) {
            Sacc[i].lo = make_float4(0.f, 0.f, 0.f, 0.f);
            Sacc[i].hi = make_float4(0.f, 0.f, 0.f, 0.f);
        }
        float scpart = 0.f;

        F8 vc[4];
        {
            const float* rowp = cb + (size_t)w * DD;
            #pragma unroll
            for (int i = 0; i < 4; i++) vc[i] = ldg_evict_last(rowp + (i * 32 + l) * 8);
        }
        #pragma unroll
        for (int j = 0; j < RPW; j++) {
            const int rl = w + j * NW;
            F8 vn[4];
            if (j + 1 < RPW) {
                const float* nrow = cb + (size_t)(rl + NW) * DD;
                #pragma unroll
                for (int i = 0; i < 4; i++) vn[i] = ldg_evict_last(nrow + (i * 32 + l) * 8);
            }
            float ss0 = 0.f, ss1 = 0.f, dd0 = 0.f, dd1 = 0.f, sd0 = 0.f, sd1 = 0.f;
            #pragma unroll
            for (int i = 0; i < 4; i++) {
                const int c = i * 32 + l;
                float4 a  = vc[i].lo;
                float4 d4 = docs[2 * c];
                float4 s4 = sums[2 * c];
                ss0 = fmaf(a.x, a.x, ss0); ss0 = fmaf(a.y, a.y, ss0);
                ss0 = fmaf(a.z, a.z, ss0); ss0 = fmaf(a.w, a.w, ss0);
                dd0 = fmaf(a.x, d4.x, dd0); dd0 = fmaf(a.y, d4.y, dd0);
                dd0 = fmaf(a.z, d4.z, dd0); dd0 = fmaf(a.w, d4.w, dd0);
                sd0 = fmaf(a.x, s4.x, sd0); sd0 = fmaf(a.y, s4.y, sd0);
                sd0 = fmaf(a.z, s4.z, sd0); sd0 = fmaf(a.w, s4.w, sd0);
                float4 a1  = vc[i].hi;
                float4 d41 = docs[2 * c + 1];
                float4 s41 = sums[2 * c + 1];
                ss1 = fmaf(a1.x, a1.x, ss1); ss1 = fmaf(a1.y, a1.y, ss1);
                ss1 = fmaf(a1.z, a1.z, ss1); ss1 = fmaf(a1.w, a1.w, ss1);
                dd1 = fmaf(a1.x, d41.x, dd1); dd1 = fmaf(a1.y, d41.y, dd1);
                dd1 = fmaf(a1.z, d41.z, dd1); dd1 = fmaf(a1.w, d41.w, dd1);
                sd1 = fmaf(a1.x, s41.x, sd1); sd1 = fmaf(a1.y, s41.y, sd1);
                sd1 = fmaf(a1.z, s41.z, sd1); sd1 = fmaf(a1.w, s41.w, sd1);
            }
            float ss = ss0 + ss1, dd = dd0 + dd1, sd = sd0 + sd1;
            #pragma unroll
            for (int o = 16; o; o >>= 1) {
                ss += __shfl_xor_sync(0xffffffffu, ss, o);
                dd += __shfl_xor_sync(0xffffffffu, dd, o);
                sd += __shfl_xor_sync(0xffffffffu, sd, o);
            }
            float rcn = rsqrtf(fmaxf(ss, EPS2));
            if (l == 0) {
                out[b * CC + row0 + rl] = dd * rcn * rdn;   // outer_score
                rcn_s[rl] = rcn;
            }
            scpart = fmaf(sd, rcn, scpart);
            #pragma unroll
            for (int i = 0; i < 4; i++) {
                Sacc[i].lo.x = fmaf(vc[i].lo.x, rcn, Sacc[i].lo.x);
                Sacc[i].lo.y = fmaf(vc[i].lo.y, rcn, Sacc[i].lo.y);
                Sacc[i].lo.z = fmaf(vc[i].lo.z, rcn, Sacc[i].lo.z);
                Sacc[i].lo.w = fmaf(vc[i].lo.w, rcn, Sacc[i].lo.w);
                Sacc[i].hi.x = fmaf(vc[i].hi.x, rcn, Sacc[i].hi.x);
                Sacc[i].hi.y = fmaf(vc[i].hi.y, rcn, Sacc[i].hi.y);
                Sacc[i].hi.z = fmaf(vc[i].hi.z, rcn, Sacc[i].hi.z);
                Sacc[i].hi.w = fmaf(vc[i].hi.w, rcn, Sacc[i].hi.w);
            }
            #pragma unroll
            for (int i = 0; i < 4; i++) vc[i] = vn[i];
        }

        // ---------- fold warp partials; publish half-S; signal ----------
        #pragma unroll
        for (int i = 0; i < 4; i++) {
            const int c = i * 32 + l;
            swp[w][2 * c]     = Sacc[i].lo;
            swp[w][2 * c + 1] = Sacc[i].hi;
        }
        if (l == 0) wsum[w] = scpart;
        __syncthreads();
        {
            float4 st = swp[0][tid];
            #pragma unroll
            for (int ww = 1; ww < NW; ww++) {
                float4 v = swp[ww][tid];
                st.x += v.x; st.y += v.y; st.z += v.z; st.w += v.w;
            }
            ((float4*)g_Spart[b][half])[tid] = st;
        }
        if (tid == 0) {
            float acc = 0.f;
            #pragma unroll
            for (int i = 0; i < NW; i++) acc += wsum[i];
            g_scpart[b][half] = acc;
        }
        __syncthreads();
        if (tid == 0) {
            __threadfence();                      // release
            atomicAdd(&g_flag[b], 1);
            while (atomicAdd(&g_flag[b], 0) < 2) { }   // wait for partner half
            __threadfence();                      // acquire
        }
        __syncthreads();

        // ---------- S = both halves; pass B re-reads own rows (L2 hits) ----------
        {
            const float4* s0 = (const float4*)g_Spart[b][0];
            const float4* s1 = (const float4*)g_Spart[b][1];
            float4 a = s0[tid];
            float4 c = s1[tid];
            a.x += c.x; a.y += c.y; a.z += c.z; a.w += c.w;
            Ssm[tid] = a;
        }
        if (half == 0 && tid == 0) {
            out[2 * BB * CC + BB + b] =
                (g_scpart[b][0] + g_scpart[b][1]) * sc_rsn * (1.0f / CC);  // summary_avg
        }
        __syncthreads();

        {
            F8 pc[4];
            const float* rowp = cb + (size_t)w * DD;
            #pragma unroll
            for (int i = 0; i < 4; i++) pc[i] = ldg_evict_first(rowp + (i * 32 + l) * 8);

            #pragma unroll
            for (int j = 0; j < RPW; j++) {
                const int rl = w + j * NW;
                F8 pn[4];
                if (j + 1 < RPW) {
                    const float* nrow = cb + (size_t)(rl + NW) * DD;
                    #pragma unroll
                    for (int i = 0; i < 4; i++) pn[i] = ldg_evict_first(nrow + (i * 32 + l) * 8);
                }
                float dot0 = 0.f, dot1 = 0.f;
                #pragma unroll
                for (int i = 0; i < 4; i++) {
                    const int c = i * 32 + l;
                    float4 a = pc[i].lo;
                    float4 s = Ssm[2 * c];
                    dot0 = fmaf(a.x, s.x, dot0); dot0 = fmaf(a.y, s.y, dot0);
                    dot0 = fmaf(a.z, s.z, dot0); dot0 = fmaf(a.w, s.w, dot0);
                    float4 a1 = pc[i].hi;
                    float4 s1 = Ssm[2 * c + 1];
                    dot1 = fmaf(a1.x, s1.x, dot1); dot1 = fmaf(a1.y, s1.y, dot1);
                    dot1 = fmaf(a1.z, s1.z, dot1); dot1 = fmaf(a1.w, s1.w, dot1);
                }
                float dot = dot0 + dot1;
                #pragma unroll
                for (int o = 16; o; o >>= 1)
                    dot += __shfl_xor_sync(0xffffffffu, dot, o);
                if (l == 0) {
                    // chat_r · S includes the self term (==1 up to fp32 rounding)
                    out[BB * CC + b * CC + row0 + rl] =
                        (dot * rcn_s[rl] - 1.0f) * (1.0f / (CC - 1));
                }
                #pragma unroll
                for (int i = 0; i < 4; i++) pc[i] = pn[i];
            }
        }
        __syncthreads();   // smem reads done before next task overwrites
    }
}

extern "C" void kernel_launch(void* const* d_in, const int* in_sizes, int n_in,
                              void* d_out, int out_size) {
    const float* doc  = (const float*)d_in[0];   // [B, D]
    const float* summ = (const float*)d_in[1];   // [B, D]
    const float* cand = (const float*)d_in[2];   // [B, C, D]
    float* out = (float*)d_out;                  // [B*C | B*C | B | B]
    (void)in_sizes; (void)n_in; (void)out_size;

    k_init_flags<<<1, BB>>>();
    k_fused<<<GRID, 256>>>(doc, summ, cand, out);
}